// round 2
// baseline (speedup 1.0000x reference)
#include <cuda_runtime.h>

#define D     128
#define NMAX  50000
#define EMAX  600000
#define GMAX  64

// ---------------- device scratch (static: no allocation allowed) -------------
__device__ float g_x1[NMAX * D];
__device__ float g_x2[NMAX * D];
__device__ float g_agg[NMAX * D];
__device__ float g_ns[NMAX];
__device__ float g_nd[NMAX];
__device__ float g_cnt[GMAX];

// ---------------- helpers ----------------------------------------------------
__device__ __forceinline__ void redv4(float* p, float4 v) {
    asm volatile(
        "{\n\t"
        ".reg .u64 gp;\n\t"
        "cvta.to.global.u64 gp, %0;\n\t"
        "red.global.add.v4.f32 [gp], {%1, %2, %3, %4};\n\t"
        "}"
        :: "l"(p), "f"(v.x), "f"(v.y), "f"(v.z), "f"(v.w)
        : "memory");
}

__device__ __forceinline__ unsigned long long pack2(float lo, float hi) {
    unsigned long long r;
    asm("mov.b64 %0, {%1, %2};" : "=l"(r) : "f"(lo), "f"(hi));
    return r;
}
__device__ __forceinline__ void unpack2(unsigned long long p, float& lo, float& hi) {
    asm("mov.b64 {%0, %1}, %2;" : "=f"(lo), "=f"(hi) : "l"(p));
}
__device__ __forceinline__ void ffma2(unsigned long long& acc,
                                      unsigned long long a, unsigned long long b) {
    asm("fma.rn.f32x2 %0, %1, %2, %0;" : "+l"(acc) : "l"(a), "l"(b));
}

// ---------------- trivial kernels --------------------------------------------
__global__ void k_zero(float* __restrict__ p, int n) {
    int i = blockIdx.x * blockDim.x + threadIdx.x;
    int stride = gridDim.x * blockDim.x;
    for (; i < n; i += stride) p[i] = 0.0f;
}

__global__ void k_degree(const int* __restrict__ src,
                         const int* __restrict__ dst,
                         float* __restrict__ ds, float* __restrict__ dd, int E) {
    int e = blockIdx.x * blockDim.x + threadIdx.x;
    if (e < E) {
        atomicAdd(&ds[src[e]], 1.0f);
        atomicAdd(&dd[dst[e]], 1.0f);
    }
}

// degrees -> rsqrt(clip(deg,1)); also accumulate per-graph node counts
__global__ void k_norm_cnt(float* __restrict__ ns, float* __restrict__ nd, int N,
                           const int* __restrict__ gid, float* __restrict__ cnt) {
    int i = blockIdx.x * blockDim.x + threadIdx.x;
    if (i < N) {
        ns[i] = rsqrtf(fmaxf(ns[i], 1.0f));
        nd[i] = rsqrtf(fmaxf(nd[i], 1.0f));
        atomicAdd(&cnt[gid[i]], 1.0f);
    }
}

// ---------------- SpMM: one warp per edge, 16B vector RED per lane -----------
__global__ __launch_bounds__(256)
void k_spmm(const float* __restrict__ x,
            const int* __restrict__ src,
            const int* __restrict__ dst,
            const float* __restrict__ ns,
            float* __restrict__ agg, int E) {
    int w    = (blockIdx.x * blockDim.x + threadIdx.x) >> 5;
    int lane = threadIdx.x & 31;
    if (w >= E) return;
    int s = src[w];
    int d = dst[w];
    float sc = __ldg(&ns[s]);
    float4 v = __ldg((const float4*)(x + (size_t)s * D) + lane);
    v.x *= sc; v.y *= sc; v.z *= sc; v.w *= sc;
    redv4((float*)((float4*)(agg + (size_t)d * D) + lane), v);
}

// ---------------- GEMM: y = relu((agg * nd[:,None]) @ W + b) -----------------
// Tile: 64 rows x 128 cols per block (256 threads; each thread 8 rows x 4 cols).
// f32x2 packed FFMA accumulators. POOL fuses the segment-mean scatter (layer 3).
template <bool POOL>
__global__ __launch_bounds__(256)
void k_gemm(const float* __restrict__ xin, const float* __restrict__ nd,
            const float* __restrict__ W, const float* __restrict__ b,
            float* __restrict__ y,
            const int* __restrict__ gid, float* __restrict__ gsum, int N) {
    __shared__ float Xs[64][D];

    int tid  = threadIdx.x;
    int tx   = tid & 31;   // column group: cols tx*4 .. tx*4+3
    int ty   = tid >> 5;   // warp id: rows ty*8 .. ty*8+7
    int row0 = blockIdx.x * 64;

    // stage scaled X tile (coalesced float4 loads, conflict-free float4 stores)
    const float4* x4 = (const float4*)xin;
#pragma unroll
    for (int it = 0; it < 8; it++) {
        int slot = tid + it * 256;           // 0..2047
        int rl = slot >> 5, c4 = slot & 31;
        int row = row0 + rl;
        float4 v = make_float4(0.f, 0.f, 0.f, 0.f);
        if (row < N) {
            v = x4[(size_t)row * 32 + c4];
            float s = __ldg(&nd[row]);
            v.x *= s; v.y *= s; v.z *= s; v.w *= s;
        }
        *(float4*)&Xs[rl][c4 * 4] = v;
    }
    __syncthreads();

    unsigned long long acc[8][2];
#pragma unroll
    for (int r = 0; r < 8; r++) { acc[r][0] = 0ull; acc[r][1] = 0ull; }

    const float4* W4 = (const float4*)W;
#pragma unroll 4
    for (int k = 0; k < 128; k++) {
        float4 w = __ldg(&W4[k * 32 + tx]);
        unsigned long long w01 = pack2(w.x, w.y);
        unsigned long long w23 = pack2(w.z, w.w);
#pragma unroll
        for (int r = 0; r < 8; r++) {
            float xv = Xs[ty * 8 + r][k];    // warp-uniform broadcast LDS
            unsigned long long xx = pack2(xv, xv);
            ffma2(acc[r][0], xx, w01);
            ffma2(acc[r][1], xx, w23);
        }
    }

    float4 bb = __ldg(((const float4*)b) + tx);

    if (!POOL) {
#pragma unroll
        for (int r = 0; r < 8; r++) {
            int row = row0 + ty * 8 + r;
            if (row < N) {
                float o0, o1, o2, o3;
                unpack2(acc[r][0], o0, o1);
                unpack2(acc[r][1], o2, o3);
                float4 o = make_float4(fmaxf(o0 + bb.x, 0.f), fmaxf(o1 + bb.y, 0.f),
                                       fmaxf(o2 + bb.z, 0.f), fmaxf(o3 + bb.w, 0.f));
                *(float4*)(y + (size_t)row * D + tx * 4) = o;
            }
        }
    } else {
        // fused per-graph sum: graph_ids are sorted, so flush-on-change
        int cur = -1;
        float4 s4 = make_float4(0.f, 0.f, 0.f, 0.f);
#pragma unroll
        for (int r = 0; r < 8; r++) {
            int row = row0 + ty * 8 + r;
            if (row >= N) break;
            float o0, o1, o2, o3;
            unpack2(acc[r][0], o0, o1);
            unpack2(acc[r][1], o2, o3);
            float4 o = make_float4(fmaxf(o0 + bb.x, 0.f), fmaxf(o1 + bb.y, 0.f),
                                   fmaxf(o2 + bb.z, 0.f), fmaxf(o3 + bb.w, 0.f));
            int g = gid[row];
            if (g != cur) {
                if (cur >= 0) redv4(gsum + (size_t)cur * D + tx * 4, s4);
                cur = g;
                s4 = o;
            } else {
                s4.x += o.x; s4.y += o.y; s4.z += o.z; s4.w += o.w;
            }
        }
        if (cur >= 0) redv4(gsum + (size_t)cur * D + tx * 4, s4);
    }
}

__global__ void k_final(float* __restrict__ out, const float* __restrict__ cnt, int n) {
    int i = blockIdx.x * blockDim.x + threadIdx.x;
    if (i < n) out[i] /= fmaxf(cnt[i >> 7], 1.0f);
}

// ---------------- launch ------------------------------------------------------
extern "C" void kernel_launch(void* const* d_in, const int* in_sizes, int n_in,
                              void* d_out, int out_size) {
    const float* h   = (const float*)d_in[0];
    const int*   src = (const int*)d_in[1];   // JAX default x64-disabled: int32
    const int*   dst = (const int*)d_in[2];
    const int*   gid = (const int*)d_in[3];
    const float* W1 = (const float*)d_in[4];
    const float* b1 = (const float*)d_in[5];
    const float* W2 = (const float*)d_in[6];
    const float* b2 = (const float*)d_in[7];
    const float* W3 = (const float*)d_in[8];
    const float* b3 = (const float*)d_in[9];

    int N = in_sizes[0] / D;
    int E = in_sizes[1];
    float* out = (float*)d_out;

    float *x1, *x2, *agg, *ns, *nd, *cnt;
    cudaGetSymbolAddress((void**)&x1,  g_x1);
    cudaGetSymbolAddress((void**)&x2,  g_x2);
    cudaGetSymbolAddress((void**)&agg, g_agg);
    cudaGetSymbolAddress((void**)&ns,  g_ns);
    cudaGetSymbolAddress((void**)&nd,  g_nd);
    cudaGetSymbolAddress((void**)&cnt, g_cnt);

    int spmmBlocks = (E * 4 + 31) / 32;     // one warp per edge, 8 warps/block
    int gemmBlocks = (N + 63) / 64;

    // init
    k_zero<<<256, 256>>>(ns, N);
    k_zero<<<256, 256>>>(nd, N);
    k_zero<<<1, 64>>>(cnt, GMAX);
    k_zero<<<32, 256>>>(out, GMAX * D);
    k_degree<<<(E + 255) / 256, 256>>>(src, dst, ns, nd, E);
    k_norm_cnt<<<(N + 255) / 256, 256>>>(ns, nd, N, gid, cnt);

    // layer 1: h -> x1
    k_zero<<<4096, 256>>>(agg, N * D);
    k_spmm<<<spmmBlocks, 256>>>(h, src, dst, ns, agg, E);
    k_gemm<false><<<gemmBlocks, 256>>>(agg, nd, W1, b1, x1, nullptr, nullptr, N);

    // layer 2: x1 -> x2
    k_zero<<<4096, 256>>>(agg, N * D);
    k_spmm<<<spmmBlocks, 256>>>(x1, src, dst, ns, agg, E);
    k_gemm<false><<<gemmBlocks, 256>>>(agg, nd, W2, b2, x2, nullptr, nullptr, N);

    // layer 3: x2 -> pooled sums directly into d_out
    k_zero<<<4096, 256>>>(agg, N * D);
    k_spmm<<<spmmBlocks, 256>>>(x2, src, dst, ns, agg, E);
    k_gemm<true><<<gemmBlocks, 256>>>(agg, nd, W3, b3, nullptr, gid, out, N);

    // mean = sum / count
    k_final<<<(GMAX * D + 255) / 256, 256>>>(out, cnt, GMAX * D);
}